// round 14
// baseline (speedup 1.0000x reference)
#include <cuda_runtime.h>
#include <math.h>

#define NN 100000
#define NE 1000000
#define EH 500000
#define NF 128
#define NH 64
#define NC 40

typedef unsigned long long ULL;

// ---------------- scratch (device globals; zero-initialized at load) --------
__device__ float g_inv[NN];       // 1/|h| per node (pass-2 only; set in agg_h)
__device__ float g_rowsum[NN];    // zeroed by agg epilogues each pass/replay
__device__ float g_ws[NN];
__device__ float g_dis[NN];
__device__ float g_sim[NE];
__device__ float g_we1[NE];       // edge-order weights pass 1 (mask for pass 2)
__device__ int4  g_slot[NE];      // {w_in bits, w_out bits, src, pad} per CSR slot
__device__ int   g_pos[NE];       // edge -> CSR slot
__device__ float g_hw[NN * NH];
__device__ float g_h[NN * NH];
__device__ float g_hw2[NN * NC];
__device__ int g_cnt[NN];         // zeroed by agg_out epilogue each replay
__device__ int g_rowstart[NN];
__device__ int g_cursor[NN];
__device__ int g_bsum[128];

__device__ __forceinline__ float warp_red_sum(float v, int width) {
    for (int o = width >> 1; o; o >>= 1) v += __shfl_xor_sync(0xffffffffu, v, o);
    return v;
}
__device__ __forceinline__ float warp_red_max(float v, int width) {
    for (int o = width >> 1; o; o >>= 1) v = fmaxf(v, __shfl_xor_sync(0xffffffffu, v, o));
    return v;
}
__device__ __forceinline__ ULL pack2(float lo, float hi) {
    ULL r; asm("mov.b64 %0, {%1, %2};" : "=l"(r) : "f"(lo), "f"(hi)); return r;
}
__device__ __forceinline__ void ffma2(ULL& d, ULL a, ULL b) {
    asm("fma.rn.f32x2 %0, %1, %2, %0;" : "+l"(d) : "l"(a), "l"(b));
}
__device__ __forceinline__ float2 unpack2(ULL v) {
    float2 r; asm("mov.b64 {%0, %1}, %2;" : "=f"(r.x), "=f"(r.y) : "l"(v)); return r;
}

// ---------------- CSR build (side-stream branch) -----------------------------
__global__ void k_hist(const int* __restrict__ dst) {
    int e = blockIdx.x * blockDim.x + threadIdx.x;
    if (e < NE) atomicAdd(&g_cnt[dst[e]], 1);   // cnt pre-zeroed by agg_out/load
}

__global__ void k_scan1() {
    cudaGridDependencySynchronize();
    int i = blockIdx.x * 1024 + threadIdx.x;
    int v = (i < NN) ? g_cnt[i] : 0;
    int lane = threadIdx.x & 31, wid = threadIdx.x >> 5;
    int x = v;
#pragma unroll
    for (int o = 1; o < 32; o <<= 1) {
        int t = __shfl_up_sync(0xffffffffu, x, o);
        if (lane >= o) x += t;
    }
    __shared__ int ws[32];
    if (lane == 31) ws[wid] = x;
    __syncthreads();
    if (wid == 0) {
        int y = ws[lane];
#pragma unroll
        for (int o = 1; o < 32; o <<= 1) {
            int t = __shfl_up_sync(0xffffffffu, y, o);
            if (lane >= o) y += t;
        }
        ws[lane] = y;
    }
    __syncthreads();
    int excl = x - v + (wid ? ws[wid - 1] : 0);
    if (i < NN) g_rowstart[i] = excl;
    if (threadIdx.x == 1023) g_bsum[blockIdx.x] = excl + v;
}

__global__ void k_scan3() {
    cudaGridDependencySynchronize();
    __shared__ int s_off;
    int blk = blockIdx.x >> 2;
    if (threadIdx.x < 32) {
        int acc = 0;
        for (int j = threadIdx.x; j < blk; j += 32) acc += g_bsum[j];
#pragma unroll
        for (int o = 16; o; o >>= 1) acc += __shfl_xor_sync(0xffffffffu, acc, o);
        if (threadIdx.x == 0) s_off = acc;
    }
    __syncthreads();
    int i = blockIdx.x * 256 + threadIdx.x;
    if (i < NN) {
        int rs = g_rowstart[i] + s_off;
        g_rowstart[i] = rs;
        g_cursor[i] = rs;
    }
}

__global__ void k_scatter(const int* __restrict__ src, const int* __restrict__ dst) {
    cudaGridDependencySynchronize();
    int e = blockIdx.x * blockDim.x + threadIdx.x;
    if (e >= EH) return;
    int s = src[e], d = dst[e];
    int p = atomicAdd(&g_cursor[d], 1);
    g_pos[e] = p; g_slot[p].z = s;
    int q = atomicAdd(&g_cursor[s], 1);
    g_pos[e + EH] = q; g_slot[q].z = d;
}

// ---- edge cosine sim on x: 8 lanes/pair, norms computed in-flight ----------
__global__ void k_sim1(const float* __restrict__ X,
                       const int* __restrict__ src, const int* __restrict__ dst) {
    int g = blockIdx.x * blockDim.x + threadIdx.x;
    int e = g >> 3, lane = g & 7;
    if (e >= EH) return;
    int s = src[e], d = dst[e];
    const float4* A = reinterpret_cast<const float4*>(X) + (size_t)s * 32;
    const float4* B = reinterpret_cast<const float4*>(X) + (size_t)d * 32;
    float pc = 0.f, ps = 0.f, pd = 0.f;
#pragma unroll
    for (int j = 0; j < 4; j++) {
        float4 a = A[lane + 8 * j];
        float4 b = B[lane + 8 * j];
        pc += a.x * b.x + a.y * b.y + a.z * b.z + a.w * b.w;
        ps += a.x * a.x + a.y * a.y + a.z * a.z + a.w * a.w;
        pd += b.x * b.x + b.y * b.y + b.z * b.z + b.w * b.w;
    }
    pc = warp_red_sum(pc, 8);
    ps = warp_red_sum(ps, 8);
    pd = warp_red_sum(pd, 8);
    if (lane == 0) {
        float is = (ps > 0.f) ? rsqrtf(ps) : 1.f;
        float id = (pd > 0.f) ? rsqrtf(pd) : 1.f;
        float raw = pc * is * id;
        if (raw < 0.1f) raw = 0.f;
        g_sim[e] = raw;
        g_sim[e + EH] = raw;
        if (raw > 0.f) {
            atomicAdd(&g_rowsum[s], raw);
            atomicAdd(&g_rowsum[d], raw);
        }
    }
}

// ---- edge cosine sim on h: 8 lanes/pair, masked by pass-1 survivors --------
__global__ void k_sim2(const int* __restrict__ src, const int* __restrict__ dst) {
    cudaGridDependencySynchronize();
    int g = blockIdx.x * blockDim.x + threadIdx.x;
    int e = g >> 3, lane = g & 7;
    if (e >= EH) return;
    int e2 = e + EH;
    bool m1 = g_we1[e] > 0.f, m2 = g_we1[e2] > 0.f;
    float p = 0.f;
    int s = 0, d = 0;
    if (m1 || m2) {
        s = src[e]; d = dst[e];
        const float4* A = reinterpret_cast<const float4*>(g_h) + (size_t)s * 16;
        const float4* B = reinterpret_cast<const float4*>(g_h) + (size_t)d * 16;
#pragma unroll
        for (int j = 0; j < 2; j++) {
            float4 a = A[lane + 8 * j];
            float4 b = B[lane + 8 * j];
            p += a.x * b.x + a.y * b.y + a.z * b.z + a.w * b.w;
        }
    }
    __syncwarp();
    p = warp_red_sum(p, 8);
    if (lane == 0) {
        if (!(m1 || m2)) { g_sim[e] = 0.f; g_sim[e2] = 0.f; return; }
        float raw = p * g_inv[s] * g_inv[d];
        if (raw < 0.1f) raw = 0.f;
        float s1 = m1 ? raw : 0.f;
        float s2 = m2 ? raw : 0.f;
        g_sim[e] = s1;
        g_sim[e2] = s2;
        if (s1 > 0.f) atomicAdd(&g_rowsum[s], s1);
        if (s2 > 0.f) atomicAdd(&g_rowsum[d], s2);
    }
}

// ------- learnable drop; writes {in,out} weight pair into slot.xy ------------
template <bool WRITE_EDGE>
__global__ void k_keep(const int* __restrict__ src, const int* __restrict__ dst,
                       const float* __restrict__ Wd, const float* __restrict__ bd) {
    cudaGridDependencySynchronize();
    int e = blockIdx.x * blockDim.x + threadIdx.x;
    if (e >= EH) return;
    int e2 = e + EH;
    float sf = g_sim[e], sb = g_sim[e2];
    int p1 = g_pos[e], p2 = g_pos[e2];
    if (!(sf > 0.f) && !(sb > 0.f)) {
        *reinterpret_cast<float2*>(&g_slot[p1]) = make_float2(0.f, 0.f);
        *reinterpret_cast<float2*>(&g_slot[p2]) = make_float2(0.f, 0.f);
        if (WRITE_EDGE) { g_we1[e] = 0.f; g_we1[e2] = 0.f; }
        return;
    }
    int s = src[e], d = dst[e];
    float rs = g_rowsum[s]; rs = (rs == 0.f) ? 1.f : rs;
    float rd = g_rowsum[d]; rd = (rd == 0.f) ? 1.f : rd;
    float af = sf / rs, ab = sb / rd;
    float w0 = Wd[0], w1 = Wd[1], bb = bd[0];
    float zf = af * w0 + ab * w1 + bb;
    float zb = ab * w0 + af * w1 + bb;
    float wf = (zf > 0.f && af > 0.f) ? expf(af) : 0.f;
    float wb = (zb > 0.f && ab > 0.f) ? expf(ab) : 0.f;
    *reinterpret_cast<float2*>(&g_slot[p1]) = make_float2(wf, wb);
    *reinterpret_cast<float2*>(&g_slot[p2]) = make_float2(wb, wf);
    if (WRITE_EDGE) { g_we1[e] = wf; g_we1[e2] = wb; }
}

// ---- finalize per node: degC/degA from CSR row sums -> ws, dis --------------
__global__ void k_fin() {
    cudaGridDependencySynchronize();
    int g = blockIdx.x * blockDim.x + threadIdx.x;
    int node = g >> 2, lane = g & 3;
    if (node >= NN) return;
    int st = g_rowstart[node], cn = g_cnt[node];
    float sw = 0.f, sa = 0.f;
    for (int i = lane; i < cn; i += 4) {
        int4 v = g_slot[st + i];
        sw += __int_as_float(v.x);       // in-weight sum -> degC
        sa += (v.y != 0) ? 1.f : 0.f;    // surviving out-edge count -> degA
    }
    __syncwarp();
    sw = warp_red_sum(sw, 4);
    sa = warp_red_sum(sa, 4);
    if (lane == 0) {
        float lam = 1.f / (sa + 1.f);
        float w = expf(lam);
        g_ws[node] = w;
        g_dis[node] = rsqrtf(sw + w + 1.f);
    }
}

// -------- GEMM Y[n,M] = X[n,K] @ W[K,M] with packed f32x2 FMA ----------------
template <int K, int M>
__global__ void k_gemm(const float* __restrict__ X, const float* __restrict__ W,
                       float* __restrict__ Y) {
    __shared__ __align__(16) float Ws[K][M];
    __shared__ float xs[128][17];
    int tid = threadIdx.x;
    int node = blockIdx.x * 128 + tid;
    for (int i = tid; i < K * M; i += 128) Ws[i / M][i % M] = W[i];
    ULL acc[M / 2];
#pragma unroll
    for (int j = 0; j < M / 2; j++) acc[j] = 0ull;
    __syncthreads();
    for (int kb = 0; kb < K; kb += 16) {
#pragma unroll
        for (int t = 0; t < 16; t++) {
            int idx = t * 128 + tid;
            int r = idx >> 4, c = idx & 15;
            int nd = blockIdx.x * 128 + r;
            xs[r][c] = (nd < NN) ? X[(size_t)nd * K + kb + c] : 0.f;
        }
        __syncthreads();
#pragma unroll
        for (int k = 0; k < 16; k++) {
            float xv = xs[tid][k];
            ULL x2 = pack2(xv, xv);
            const ULL* wrow = reinterpret_cast<const ULL*>(&Ws[kb + k][0]);
#pragma unroll
            for (int j = 0; j < M / 2; j++) ffma2(acc[j], wrow[j], x2);
        }
        __syncthreads();
    }
    if (node < NN) {
#pragma unroll
        for (int j = 0; j < M / 2; j += 2) {
            float2 lo = unpack2(acc[j]), hi = unpack2(acc[j + 1]);
            *reinterpret_cast<float4*>(&Y[(size_t)node * M + 2 * j]) =
                make_float4(lo.x, lo.y, hi.x, hi.y);
        }
    }
}

// ---- conv1 agg (single 16B slot load per edge) + bias+relu + pass-2 norm ----
__global__ void k_agg_h(const float* __restrict__ b1) {
    cudaGridDependencySynchronize();
    int g = blockIdx.x * blockDim.x + threadIdx.x;
    int node = g >> 4, lane = g & 15;
    if (node >= NN) return;
    const float4* hw4 = reinterpret_cast<const float4*>(g_hw);
    float dd = g_dis[node];
    float self = dd * (g_ws[node] + 1.f);
    float4 v = hw4[node * 16 + lane];
    float4 a  = make_float4(self * v.x, self * v.y, self * v.z, self * v.w);
    float4 a2 = make_float4(0.f, 0.f, 0.f, 0.f);
    int st = g_rowstart[node], cn = g_cnt[node];
    int i = 0;
    for (; i + 1 < cn; i += 2) {
        int4 t0 = g_slot[st + i];
        int4 t1 = g_slot[st + i + 1];
        float c0 = g_dis[t0.z] * __int_as_float(t0.x);
        float c1 = g_dis[t1.z] * __int_as_float(t1.x);
        float4 u0 = hw4[(size_t)t0.z * 16 + lane];
        float4 u1 = hw4[(size_t)t1.z * 16 + lane];
        a.x  += c0 * u0.x; a.y  += c0 * u0.y; a.z  += c0 * u0.z; a.w  += c0 * u0.w;
        a2.x += c1 * u1.x; a2.y += c1 * u1.y; a2.z += c1 * u1.z; a2.w += c1 * u1.w;
    }
    if (i < cn) {
        int4 t0 = g_slot[st + i];
        float c0 = g_dis[t0.z] * __int_as_float(t0.x);
        float4 u0 = hw4[(size_t)t0.z * 16 + lane];
        a.x += c0 * u0.x; a.y += c0 * u0.y; a.z += c0 * u0.z; a.w += c0 * u0.w;
    }
    a.x += a2.x; a.y += a2.y; a.z += a2.z; a.w += a2.w;
    float4 b = reinterpret_cast<const float4*>(b1)[lane];
    float4 h;
    h.x = fmaxf(dd * a.x + b.x, 0.f);
    h.y = fmaxf(dd * a.y + b.y, 0.f);
    h.z = fmaxf(dd * a.z + b.z, 0.f);
    h.w = fmaxf(dd * a.w + b.w, 0.f);
    reinterpret_cast<float4*>(g_h)[node * 16 + lane] = h;
    float ss = h.x * h.x + h.y * h.y + h.z * h.z + h.w * h.w;
    __syncwarp();
    ss = warp_red_sum(ss, 16);
    if (lane == 0) {   // pass-2 norm + rowsum re-zero for pass 2
        g_inv[node] = (ss == 0.f) ? 1.f : rsqrtf(ss);
        g_rowsum[node] = 0.f;
    }
}

// ---- conv2 agg + bias + log_softmax, 8 lanes/node (float4 + scalar) ---------
__global__ void k_agg_out(const float* __restrict__ b2, float* __restrict__ out) {
    cudaGridDependencySynchronize();
    int g = blockIdx.x * blockDim.x + threadIdx.x;
    int node = g >> 3, lane = g & 7;
    if (node >= NN) return;
    const float* hp = g_hw2;
    float dd = g_dis[node];
    float self = dd * (g_ws[node] + 1.f);
    const float* row = hp + (size_t)node * NC;
    float4 v4 = *reinterpret_cast<const float4*>(row + lane * 4);
    float  v1 = row[32 + lane];
    float4 a4 = make_float4(self * v4.x, self * v4.y, self * v4.z, self * v4.w);
    float  a1 = self * v1;
    int st = g_rowstart[node], cn = g_cnt[node];
    int i = 0;
    for (; i + 1 < cn; i += 2) {
        int4 t0 = g_slot[st + i];
        int4 t1 = g_slot[st + i + 1];
        float c0 = g_dis[t0.z] * __int_as_float(t0.x);
        float c1 = g_dis[t1.z] * __int_as_float(t1.x);
        const float* r0 = hp + (size_t)t0.z * NC;
        const float* r1 = hp + (size_t)t1.z * NC;
        float4 u0 = *reinterpret_cast<const float4*>(r0 + lane * 4);
        float4 u1 = *reinterpret_cast<const float4*>(r1 + lane * 4);
        float  e0 = r0[32 + lane];
        float  e1 = r1[32 + lane];
        a4.x += c0 * u0.x; a4.y += c0 * u0.y; a4.z += c0 * u0.z; a4.w += c0 * u0.w;
        a1   += c0 * e0;
        a4.x += c1 * u1.x; a4.y += c1 * u1.y; a4.z += c1 * u1.z; a4.w += c1 * u1.w;
        a1   += c1 * e1;
    }
    if (i < cn) {
        int4 t0 = g_slot[st + i];
        float c0 = g_dis[t0.z] * __int_as_float(t0.x);
        const float* r0 = hp + (size_t)t0.z * NC;
        float4 u0 = *reinterpret_cast<const float4*>(r0 + lane * 4);
        float  e0 = r0[32 + lane];
        a4.x += c0 * u0.x; a4.y += c0 * u0.y; a4.z += c0 * u0.z; a4.w += c0 * u0.w;
        a1   += c0 * e0;
    }
    float4 bb4 = *reinterpret_cast<const float4*>(b2 + lane * 4);
    float  bb1 = b2[32 + lane];
    float4 o4;
    o4.x = dd * a4.x + bb4.x; o4.y = dd * a4.y + bb4.y;
    o4.z = dd * a4.z + bb4.z; o4.w = dd * a4.w + bb4.w;
    float o1 = dd * a1 + bb1;
    float mx = fmaxf(fmaxf(fmaxf(o4.x, o4.y), fmaxf(o4.z, o4.w)), o1);
    __syncwarp();
    float m = warp_red_max(mx, 8);
    float es = expf(o4.x - m) + expf(o4.y - m) + expf(o4.z - m) + expf(o4.w - m)
             + expf(o1 - m);
    es = warp_red_sum(es, 8);
    float lse = logf(es) + m;
    float* orow = out + (size_t)node * NC;
    *reinterpret_cast<float4*>(orow + lane * 4) =
        make_float4(o4.x - lse, o4.y - lse, o4.z - lse, o4.w - lse);
    orow[32 + lane] = o1 - lse;
    if (lane == 0) {   // re-arm for the next replay
        g_cnt[node] = 0;
        g_rowsum[node] = 0.f;
    }
}

// ---------------- PDL launch helper -------------------------------------------
template <typename F, typename... Args>
static void launch_pdl(F kern, int grid, int block, cudaStream_t st, Args... args) {
    cudaLaunchConfig_t cfg = {};
    cfg.gridDim = dim3(grid, 1, 1);
    cfg.blockDim = dim3(block, 1, 1);
    cfg.stream = st;
    cudaLaunchAttribute attr[1];
    attr[0].id = cudaLaunchAttributeProgrammaticStreamSerialization;
    attr[0].val.programmaticStreamSerializationAllowed = 1;
    cfg.attrs = attr;
    cfg.numAttrs = 1;
    cudaLaunchKernelEx(&cfg, kern, args...);
}

// ---------------- host driver (fork-join branches + PDL) ----------------------
extern "C" void kernel_launch(void* const* d_in, const int* in_sizes, int n_in,
                              void* d_out, int out_size) {
    const float* x  = (const float*)d_in[0];
    const int* src  = (const int*)d_in[1];
    const int* dst  = (const int*)d_in[2];
    const float* W1 = (const float*)d_in[4];
    const float* b1 = (const float*)d_in[5];
    const float* W2 = (const float*)d_in[6];
    const float* b2 = (const float*)d_in[7];
    const float* Wd = (const float*)d_in[8];
    const float* bd = (const float*)d_in[9];
    float* out = (float*)d_out;

    float *p_hw, *p_h, *p_hw2;
    cudaGetSymbolAddress((void**)&p_hw,  g_hw);
    cudaGetSymbolAddress((void**)&p_h,   g_h);
    cudaGetSymbolAddress((void**)&p_hw2, g_hw2);

    const int TB = 256;
    int gb_node8     = (NN * 8 + TB - 1) / TB;
    int gb_node_half = (NN * 16 + TB - 1) / TB;
    int gb_node4     = (NN * 4 + TB - 1) / TB;
    int gb_edge      = (NE + TB - 1) / TB;
    int gb_pair      = (EH + TB - 1) / TB;
    int gb_pair8     = (EH * 8 + TB - 1) / TB;
    int gb_gemm      = (NN + 127) / 128;
    int nb_scan      = (NN + 1023) / 1024;

    cudaStream_t s1, s2;
    cudaStreamCreate(&s1);
    cudaStreamCreate(&s2);
    cudaEvent_t ev0, ev1, ev2, ev3, evCsr;
    cudaEventCreateWithFlags(&ev0,   cudaEventDisableTiming);
    cudaEventCreateWithFlags(&ev1,   cudaEventDisableTiming);
    cudaEventCreateWithFlags(&ev2,   cudaEventDisableTiming);
    cudaEventCreateWithFlags(&ev3,   cudaEventDisableTiming);
    cudaEventCreateWithFlags(&evCsr, cudaEventDisableTiming);

    // ---- fork A: gemm1 on s1 (depends only on x, W1) ----
    cudaEventRecord(ev0, 0);
    cudaStreamWaitEvent(s1, ev0, 0);
    k_gemm<NF, NH><<<gb_gemm, 128, 0, s1>>>(x, W1, p_hw);
    cudaEventRecord(ev1, s1);

    // ---- fork B: CSR build on s2 (hist -> scans -> scatter, all hidden) ----
    cudaStreamWaitEvent(s2, ev0, 0);
    k_hist<<<gb_edge, TB, 0, s2>>>(dst);
    launch_pdl(k_scan1, nb_scan, 1024, s2);
    launch_pdl(k_scan3, (NN + 255) / 256, 256, s2);
    launch_pdl(k_scatter, gb_pair, TB, s2, src, dst);
    cudaEventRecord(evCsr, s2);

    // ---- main chain: sim1 (self-norming) ----
    k_sim1<<<gb_pair8, TB>>>(x, src, dst);

    // ---- join CSR branch, attention pass 1 ----
    cudaStreamWaitEvent(0, evCsr, 0);
    launch_pdl(k_keep<true>, gb_pair, TB, (cudaStream_t)0, src, dst, Wd, bd);
    launch_pdl(k_fin, gb_node4, TB, (cudaStream_t)0);

    // ---- join gemm1, conv1 aggregate ----
    cudaStreamWaitEvent(0, ev1, 0);
    launch_pdl(k_agg_h, gb_node_half, TB, (cudaStream_t)0, b1);

    // ---- fork: gemm2 on s1 (depends only on h, W2) ----
    cudaEventRecord(ev2, 0);
    cudaStreamWaitEvent(s1, ev2, 0);
    k_gemm<NH, NC><<<gb_gemm, 128, 0, s1>>>(p_h, W2, p_hw2);
    cudaEventRecord(ev3, s1);

    // ---- main chain: attention pass 2 ----
    launch_pdl(k_sim2, gb_pair8, TB, (cudaStream_t)0, src, dst);
    launch_pdl(k_keep<false>, gb_pair, TB, (cudaStream_t)0, src, dst, Wd, bd);
    launch_pdl(k_fin, gb_node4, TB, (cudaStream_t)0);

    // ---- join gemm2, conv2 aggregate + log_softmax ----
    cudaStreamWaitEvent(0, ev3, 0);
    launch_pdl(k_agg_out, gb_node8, TB, (cudaStream_t)0, b2, out);

    // Destroy host-side objects only when not inside a capture.
    cudaStreamCaptureStatus cs = cudaStreamCaptureStatusNone;
    cudaStreamIsCapturing((cudaStream_t)0, &cs);
    if (cs == cudaStreamCaptureStatusNone) {
        cudaEventDestroy(ev0); cudaEventDestroy(ev1);
        cudaEventDestroy(ev2); cudaEventDestroy(ev3);
        cudaEventDestroy(evCsr);
        cudaStreamDestroy(s1); cudaStreamDestroy(s2);
    }
}

// round 15
// speedup vs baseline: 1.0844x; 1.0844x over previous
#include <cuda_runtime.h>
#include <math.h>

#define NN 100000
#define NE 1000000
#define EH 500000
#define NF 128
#define NH 64
#define NC 40
#define PGRID 1184   // 8 blocks/SM × 148 SMs

typedef unsigned long long ULL;

// ---------------- scratch (device globals; zero-initialized at load) --------
__device__ float g_inv[NN];
__device__ float g_rowsum[NN];    // zeroed by agg epilogues each pass/replay
__device__ float g_ws[NN];
__device__ float g_dis[NN];
__device__ float g_sim[NE];
__device__ unsigned char g_mask[NE];  // pass-1 survivor mask
__device__ float2 g_csrw[NE];     // CSR slot: {in-weight, out-weight}
__device__ int   g_pos[NE];       // edge -> CSR slot
__device__ int   g_srccs[NE];     // CSR-ordered source node
__device__ float g_hw[NN * NH];
__device__ float g_h[NN * NH];
__device__ float g_hw2[NN * NC];
__device__ int g_cnt[NN];         // zeroed by agg_out epilogue each replay
__device__ int g_rowstart[NN];
__device__ int g_cursor[NN];
__device__ int g_bsum[128];

__device__ __forceinline__ float warp_red_sum(float v, int width) {
    for (int o = width >> 1; o; o >>= 1) v += __shfl_xor_sync(0xffffffffu, v, o);
    return v;
}
__device__ __forceinline__ float warp_red_max(float v, int width) {
    for (int o = width >> 1; o; o >>= 1) v = fmaxf(v, __shfl_xor_sync(0xffffffffu, v, o));
    return v;
}
__device__ __forceinline__ ULL pack2(float lo, float hi) {
    ULL r; asm("mov.b64 %0, {%1, %2};" : "=l"(r) : "f"(lo), "f"(hi)); return r;
}
__device__ __forceinline__ void ffma2(ULL& d, ULL a, ULL b) {
    asm("fma.rn.f32x2 %0, %1, %2, %0;" : "+l"(d) : "l"(a), "l"(b));
}
__device__ __forceinline__ float2 unpack2(ULL v) {
    float2 r; asm("mov.b64 {%0, %1}, %2;" : "=f"(r.x), "=f"(r.y) : "l"(v)); return r;
}

// ---------------- CSR build (side-stream branch) -----------------------------
__global__ void k_hist(const int* __restrict__ dst) {
    int e = blockIdx.x * blockDim.x + threadIdx.x;
    if (e < NE) atomicAdd(&g_cnt[dst[e]], 1);
}

__global__ void k_scan1() {
    cudaGridDependencySynchronize();
    int i = blockIdx.x * 1024 + threadIdx.x;
    int v = (i < NN) ? g_cnt[i] : 0;
    int lane = threadIdx.x & 31, wid = threadIdx.x >> 5;
    int x = v;
#pragma unroll
    for (int o = 1; o < 32; o <<= 1) {
        int t = __shfl_up_sync(0xffffffffu, x, o);
        if (lane >= o) x += t;
    }
    __shared__ int ws[32];
    if (lane == 31) ws[wid] = x;
    __syncthreads();
    if (wid == 0) {
        int y = ws[lane];
#pragma unroll
        for (int o = 1; o < 32; o <<= 1) {
            int t = __shfl_up_sync(0xffffffffu, y, o);
            if (lane >= o) y += t;
        }
        ws[lane] = y;
    }
    __syncthreads();
    int excl = x - v + (wid ? ws[wid - 1] : 0);
    if (i < NN) g_rowstart[i] = excl;
    if (threadIdx.x == 1023) g_bsum[blockIdx.x] = excl + v;
}

__global__ void k_scan3() {
    cudaGridDependencySynchronize();
    __shared__ int s_off;
    int blk = blockIdx.x >> 2;
    if (threadIdx.x < 32) {
        int acc = 0;
        for (int j = threadIdx.x; j < blk; j += 32) acc += g_bsum[j];
#pragma unroll
        for (int o = 16; o; o >>= 1) acc += __shfl_xor_sync(0xffffffffu, acc, o);
        if (threadIdx.x == 0) s_off = acc;
    }
    __syncthreads();
    int i = blockIdx.x * 256 + threadIdx.x;
    if (i < NN) {
        int rs = g_rowstart[i] + s_off;
        g_rowstart[i] = rs;
        g_cursor[i] = rs;
    }
}

__global__ void k_scatter(const int* __restrict__ src, const int* __restrict__ dst) {
    cudaGridDependencySynchronize();
    int e = blockIdx.x * blockDim.x + threadIdx.x;
    if (e >= EH) return;
    int s = src[e], d = dst[e];
    int p = atomicAdd(&g_cursor[d], 1);
    g_pos[e] = p; g_srccs[p] = s;
    int q = atomicAdd(&g_cursor[s], 1);
    g_pos[e + EH] = q; g_srccs[q] = d;
}

// ---- edge cosine sim on x: 8 lanes/pair, grid-stride, norms in-flight -------
__global__ void k_sim1(const float* __restrict__ X,
                       const int* __restrict__ src, const int* __restrict__ dst) {
    int lane = threadIdx.x & 7;
    int groups = (gridDim.x * blockDim.x) >> 3;
    for (int e = (blockIdx.x * blockDim.x + threadIdx.x) >> 3; e < EH; e += groups) {
        int s = src[e], d = dst[e];
        const float4* A = reinterpret_cast<const float4*>(X) + (size_t)s * 32;
        const float4* B = reinterpret_cast<const float4*>(X) + (size_t)d * 32;
        float pc = 0.f, ps = 0.f, pd = 0.f;
#pragma unroll
        for (int j = 0; j < 4; j++) {
            float4 a = A[lane + 8 * j];
            float4 b = B[lane + 8 * j];
            pc += a.x * b.x + a.y * b.y + a.z * b.z + a.w * b.w;
            ps += a.x * a.x + a.y * a.y + a.z * a.z + a.w * a.w;
            pd += b.x * b.x + b.y * b.y + b.z * b.z + b.w * b.w;
        }
        pc = warp_red_sum(pc, 8);
        ps = warp_red_sum(ps, 8);
        pd = warp_red_sum(pd, 8);
        if (lane == 0) {
            float is = (ps > 0.f) ? rsqrtf(ps) : 1.f;
            float id = (pd > 0.f) ? rsqrtf(pd) : 1.f;
            float raw = pc * is * id;
            if (raw < 0.1f) raw = 0.f;
            g_sim[e] = raw;   // symmetric in pass 1; keep mirrors
            if (raw > 0.f) {
                atomicAdd(&g_rowsum[s], raw);
                atomicAdd(&g_rowsum[d], raw);
            }
        }
    }
}

// ---- edge cosine sim on h: 8 lanes/pair, grid-stride, byte mask -------------
__global__ void k_sim2(const int* __restrict__ src, const int* __restrict__ dst) {
    cudaGridDependencySynchronize();
    int lane = threadIdx.x & 7;
    int groups = (gridDim.x * blockDim.x) >> 3;
    for (int e = (blockIdx.x * blockDim.x + threadIdx.x) >> 3; e < EH; e += groups) {
        int e2 = e + EH;
        bool m1 = g_mask[e] != 0, m2 = g_mask[e2] != 0;
        float p = 0.f;
        int s = 0, d = 0;
        if (m1 || m2) {
            s = src[e]; d = dst[e];
            const float4* A = reinterpret_cast<const float4*>(g_h) + (size_t)s * 16;
            const float4* B = reinterpret_cast<const float4*>(g_h) + (size_t)d * 16;
#pragma unroll
            for (int j = 0; j < 2; j++) {
                float4 a = A[lane + 8 * j];
                float4 b = B[lane + 8 * j];
                p += a.x * b.x + a.y * b.y + a.z * b.z + a.w * b.w;
            }
        }
        __syncwarp();
        p = warp_red_sum(p, 8);
        if (lane == 0) {
            if (!(m1 || m2)) { g_sim[e] = 0.f; g_sim[e2] = 0.f; continue; }
            float raw = p * g_inv[s] * g_inv[d];
            if (raw < 0.1f) raw = 0.f;
            float s1 = m1 ? raw : 0.f;
            float s2 = m2 ? raw : 0.f;
            g_sim[e] = s1;
            g_sim[e2] = s2;
            if (s1 > 0.f) atomicAdd(&g_rowsum[s], s1);
            if (s2 > 0.f) atomicAdd(&g_rowsum[d], s2);
        }
    }
}

// ------- learnable drop; writes {in,out} float2 to CSR slots, grid-stride ----
template <bool PASS1>
__global__ void k_keep(const int* __restrict__ src, const int* __restrict__ dst,
                       const float* __restrict__ Wd, const float* __restrict__ bd) {
    cudaGridDependencySynchronize();
    int stride = gridDim.x * blockDim.x;
    for (int e = blockIdx.x * blockDim.x + threadIdx.x; e < EH; e += stride) {
        int e2 = e + EH;
        float sf, sb;
        if (PASS1) { sf = g_sim[e]; sb = sf; }
        else       { sf = g_sim[e]; sb = g_sim[e2]; }
        int p1 = g_pos[e], p2 = g_pos[e2];
        if (!(sf > 0.f) && !(sb > 0.f)) {
            g_csrw[p1] = make_float2(0.f, 0.f);
            g_csrw[p2] = make_float2(0.f, 0.f);
            if (PASS1) { g_mask[e] = 0; g_mask[e2] = 0; }
            continue;
        }
        int s = src[e], d = dst[e];
        float rs = g_rowsum[s]; rs = (rs == 0.f) ? 1.f : rs;
        float rd = g_rowsum[d]; rd = (rd == 0.f) ? 1.f : rd;
        float af = sf / rs, ab = sb / rd;
        float w0 = Wd[0], w1 = Wd[1], bb = bd[0];
        float zf = af * w0 + ab * w1 + bb;
        float zb = ab * w0 + af * w1 + bb;
        float wf = (zf > 0.f && af > 0.f) ? expf(af) : 0.f;
        float wb = (zb > 0.f && ab > 0.f) ? expf(ab) : 0.f;
        g_csrw[p1] = make_float2(wf, wb);
        g_csrw[p2] = make_float2(wb, wf);
        if (PASS1) {
            g_mask[e]  = (wf > 0.f) ? 1 : 0;
            g_mask[e2] = (wb > 0.f) ? 1 : 0;
        }
    }
}

// ---- finalize per node: degC/degA from CSR row sums -> ws, dis --------------
__global__ void k_fin() {
    cudaGridDependencySynchronize();
    int g = blockIdx.x * blockDim.x + threadIdx.x;
    int node = g >> 2, lane = g & 3;
    if (node >= NN) return;
    int st = g_rowstart[node], cn = g_cnt[node];
    float sw = 0.f, sa = 0.f;
    for (int i = lane; i < cn; i += 4) {
        float2 w = g_csrw[st + i];
        sw += w.x;
        sa += (w.y != 0.f) ? 1.f : 0.f;
    }
    __syncwarp();
    sw = warp_red_sum(sw, 4);
    sa = warp_red_sum(sa, 4);
    if (lane == 0) {
        float lam = 1.f / (sa + 1.f);
        float w = expf(lam);
        g_ws[node] = w;
        g_dis[node] = rsqrtf(sw + w + 1.f);
    }
}

// -------- GEMM Y[n,M] = X[n,K] @ W[K,M] with packed f32x2 FMA ----------------
template <int K, int M>
__global__ void k_gemm(const float* __restrict__ X, const float* __restrict__ W,
                       float* __restrict__ Y) {
    __shared__ __align__(16) float Ws[K][M];
    __shared__ float xs[128][17];
    int tid = threadIdx.x;
    int node = blockIdx.x * 128 + tid;
    for (int i = tid; i < K * M; i += 128) Ws[i / M][i % M] = W[i];
    ULL acc[M / 2];
#pragma unroll
    for (int j = 0; j < M / 2; j++) acc[j] = 0ull;
    __syncthreads();
    for (int kb = 0; kb < K; kb += 16) {
#pragma unroll
        for (int t = 0; t < 16; t++) {
            int idx = t * 128 + tid;
            int r = idx >> 4, c = idx & 15;
            int nd = blockIdx.x * 128 + r;
            xs[r][c] = (nd < NN) ? X[(size_t)nd * K + kb + c] : 0.f;
        }
        __syncthreads();
#pragma unroll
        for (int k = 0; k < 16; k++) {
            float xv = xs[tid][k];
            ULL x2 = pack2(xv, xv);
            const ULL* wrow = reinterpret_cast<const ULL*>(&Ws[kb + k][0]);
#pragma unroll
            for (int j = 0; j < M / 2; j++) ffma2(acc[j], wrow[j], x2);
        }
        __syncthreads();
    }
    if (node < NN) {
#pragma unroll
        for (int j = 0; j < M / 2; j += 2) {
            float2 lo = unpack2(acc[j]), hi = unpack2(acc[j + 1]);
            *reinterpret_cast<float4*>(&Y[(size_t)node * M + 2 * j]) =
                make_float4(lo.x, lo.y, hi.x, hi.y);
        }
    }
}

// ---- conv1 agg (grid-stride, 16 lanes/node) + bias+relu + pass-2 norm -------
__global__ void k_agg_h(const float* __restrict__ b1) {
    cudaGridDependencySynchronize();
    int lane = threadIdx.x & 15;
    int groups = (gridDim.x * blockDim.x) >> 4;
    const float4* hw4 = reinterpret_cast<const float4*>(g_hw);
    for (int node = (blockIdx.x * blockDim.x + threadIdx.x) >> 4; node < NN;
         node += groups) {
        float dd = g_dis[node];
        float self = dd * (g_ws[node] + 1.f);
        float4 v = hw4[node * 16 + lane];
        float4 a  = make_float4(self * v.x, self * v.y, self * v.z, self * v.w);
        float4 a2 = make_float4(0.f, 0.f, 0.f, 0.f);
        int st = g_rowstart[node], cn = g_cnt[node];
        int i = 0;
        for (; i + 1 < cn; i += 2) {
            float w0 = g_csrw[st + i].x, w1v = g_csrw[st + i + 1].x;
            int   s0 = g_srccs[st + i],  s1v = g_srccs[st + i + 1];
            float c0 = g_dis[s0] * w0;
            float c1 = g_dis[s1v] * w1v;
            float4 u0 = hw4[(size_t)s0 * 16 + lane];
            float4 u1 = hw4[(size_t)s1v * 16 + lane];
            a.x  += c0 * u0.x; a.y  += c0 * u0.y; a.z  += c0 * u0.z; a.w  += c0 * u0.w;
            a2.x += c1 * u1.x; a2.y += c1 * u1.y; a2.z += c1 * u1.z; a2.w += c1 * u1.w;
        }
        if (i < cn) {
            float w0 = g_csrw[st + i].x;
            int s0 = g_srccs[st + i];
            float c0 = g_dis[s0] * w0;
            float4 u0 = hw4[(size_t)s0 * 16 + lane];
            a.x += c0 * u0.x; a.y += c0 * u0.y; a.z += c0 * u0.z; a.w += c0 * u0.w;
        }
        a.x += a2.x; a.y += a2.y; a.z += a2.z; a.w += a2.w;
        float4 b = reinterpret_cast<const float4*>(b1)[lane];
        float4 h;
        h.x = fmaxf(dd * a.x + b.x, 0.f);
        h.y = fmaxf(dd * a.y + b.y, 0.f);
        h.z = fmaxf(dd * a.z + b.z, 0.f);
        h.w = fmaxf(dd * a.w + b.w, 0.f);
        reinterpret_cast<float4*>(g_h)[node * 16 + lane] = h;
        float ss = h.x * h.x + h.y * h.y + h.z * h.z + h.w * h.w;
        __syncwarp();
        ss = warp_red_sum(ss, 16);
        if (lane == 0) {
            g_inv[node] = (ss == 0.f) ? 1.f : rsqrtf(ss);
            g_rowsum[node] = 0.f;
        }
    }
}

// ---- conv2 agg + bias + log_softmax, grid-stride, 8 lanes/node --------------
__global__ void k_agg_out(const float* __restrict__ b2, float* __restrict__ out) {
    cudaGridDependencySynchronize();
    int lane = threadIdx.x & 7;
    int groups = (gridDim.x * blockDim.x) >> 3;
    const float* hp = g_hw2;
    for (int node = (blockIdx.x * blockDim.x + threadIdx.x) >> 3; node < NN;
         node += groups) {
        float dd = g_dis[node];
        float self = dd * (g_ws[node] + 1.f);
        const float* row = hp + (size_t)node * NC;
        float4 v4 = *reinterpret_cast<const float4*>(row + lane * 4);
        float  v1 = row[32 + lane];
        float4 a4 = make_float4(self * v4.x, self * v4.y, self * v4.z, self * v4.w);
        float  a1 = self * v1;
        int st = g_rowstart[node], cn = g_cnt[node];
        int i = 0;
        for (; i + 1 < cn; i += 2) {
            float w0 = g_csrw[st + i].x, w1v = g_csrw[st + i + 1].x;
            int   s0 = g_srccs[st + i],  s1v = g_srccs[st + i + 1];
            float c0 = g_dis[s0] * w0;
            float c1 = g_dis[s1v] * w1v;
            const float* r0 = hp + (size_t)s0 * NC;
            const float* r1 = hp + (size_t)s1v * NC;
            float4 u0 = *reinterpret_cast<const float4*>(r0 + lane * 4);
            float4 u1 = *reinterpret_cast<const float4*>(r1 + lane * 4);
            float  e0 = r0[32 + lane];
            float  e1 = r1[32 + lane];
            a4.x += c0 * u0.x; a4.y += c0 * u0.y; a4.z += c0 * u0.z; a4.w += c0 * u0.w;
            a1   += c0 * e0;
            a4.x += c1 * u1.x; a4.y += c1 * u1.y; a4.z += c1 * u1.z; a4.w += c1 * u1.w;
            a1   += c1 * e1;
        }
        if (i < cn) {
            float w0 = g_csrw[st + i].x;
            int s0 = g_srccs[st + i];
            float c0 = g_dis[s0] * w0;
            const float* r0 = hp + (size_t)s0 * NC;
            float4 u0 = *reinterpret_cast<const float4*>(r0 + lane * 4);
            float  e0 = r0[32 + lane];
            a4.x += c0 * u0.x; a4.y += c0 * u0.y; a4.z += c0 * u0.z; a4.w += c0 * u0.w;
            a1   += c0 * e0;
        }
        float4 bb4 = *reinterpret_cast<const float4*>(b2 + lane * 4);
        float  bb1 = b2[32 + lane];
        float4 o4;
        o4.x = dd * a4.x + bb4.x; o4.y = dd * a4.y + bb4.y;
        o4.z = dd * a4.z + bb4.z; o4.w = dd * a4.w + bb4.w;
        float o1 = dd * a1 + bb1;
        float mx = fmaxf(fmaxf(fmaxf(o4.x, o4.y), fmaxf(o4.z, o4.w)), o1);
        __syncwarp();
        float m = warp_red_max(mx, 8);
        float es = expf(o4.x - m) + expf(o4.y - m) + expf(o4.z - m) + expf(o4.w - m)
                 + expf(o1 - m);
        es = warp_red_sum(es, 8);
        float lse = logf(es) + m;
        float* orow = out + (size_t)node * NC;
        *reinterpret_cast<float4*>(orow + lane * 4) =
            make_float4(o4.x - lse, o4.y - lse, o4.z - lse, o4.w - lse);
        orow[32 + lane] = o1 - lse;
        if (lane == 0) {   // re-arm for the next replay
            g_cnt[node] = 0;
            g_rowsum[node] = 0.f;
        }
    }
}

// ---------------- PDL launch helper -------------------------------------------
template <typename F, typename... Args>
static void launch_pdl(F kern, int grid, int block, cudaStream_t st, Args... args) {
    cudaLaunchConfig_t cfg = {};
    cfg.gridDim = dim3(grid, 1, 1);
    cfg.blockDim = dim3(block, 1, 1);
    cfg.stream = st;
    cudaLaunchAttribute attr[1];
    attr[0].id = cudaLaunchAttributeProgrammaticStreamSerialization;
    attr[0].val.programmaticStreamSerializationAllowed = 1;
    cfg.attrs = attr;
    cfg.numAttrs = 1;
    cudaLaunchKernelEx(&cfg, kern, args...);
}

// ---------------- host driver (fork-join branches + PDL) ----------------------
extern "C" void kernel_launch(void* const* d_in, const int* in_sizes, int n_in,
                              void* d_out, int out_size) {
    const float* x  = (const float*)d_in[0];
    const int* src  = (const int*)d_in[1];
    const int* dst  = (const int*)d_in[2];
    const float* W1 = (const float*)d_in[4];
    const float* b1 = (const float*)d_in[5];
    const float* W2 = (const float*)d_in[6];
    const float* b2 = (const float*)d_in[7];
    const float* Wd = (const float*)d_in[8];
    const float* bd = (const float*)d_in[9];
    float* out = (float*)d_out;

    float *p_hw, *p_h, *p_hw2;
    cudaGetSymbolAddress((void**)&p_hw,  g_hw);
    cudaGetSymbolAddress((void**)&p_h,   g_h);
    cudaGetSymbolAddress((void**)&p_hw2, g_hw2);

    const int TB = 256;
    int gb_node4 = (NN * 4 + TB - 1) / TB;
    int gb_edge  = (NE + TB - 1) / TB;
    int gb_pair  = (EH + TB - 1) / TB;
    int gb_gemm  = (NN + 127) / 128;
    int nb_scan  = (NN + 1023) / 1024;

    cudaStream_t s1, s2;
    cudaStreamCreate(&s1);
    cudaStreamCreate(&s2);
    cudaEvent_t ev0, ev1, ev2, ev3, evCsr;
    cudaEventCreateWithFlags(&ev0,   cudaEventDisableTiming);
    cudaEventCreateWithFlags(&ev1,   cudaEventDisableTiming);
    cudaEventCreateWithFlags(&ev2,   cudaEventDisableTiming);
    cudaEventCreateWithFlags(&ev3,   cudaEventDisableTiming);
    cudaEventCreateWithFlags(&evCsr, cudaEventDisableTiming);

    // ---- fork A: gemm1 on s1 (depends only on x, W1) ----
    cudaEventRecord(ev0, 0);
    cudaStreamWaitEvent(s1, ev0, 0);
    k_gemm<NF, NH><<<gb_gemm, 128, 0, s1>>>(x, W1, p_hw);
    cudaEventRecord(ev1, s1);

    // ---- fork B: CSR build on s2 (hist -> scans -> scatter, hidden) ----
    cudaStreamWaitEvent(s2, ev0, 0);
    k_hist<<<gb_edge, TB, 0, s2>>>(dst);
    launch_pdl(k_scan1, nb_scan, 1024, s2);
    launch_pdl(k_scan3, (NN + 255) / 256, 256, s2);
    launch_pdl(k_scatter, gb_pair, TB, s2, src, dst);
    cudaEventRecord(evCsr, s2);

    // ---- main chain: sim1 (self-norming, persistent) ----
    k_sim1<<<PGRID, TB>>>(x, src, dst);

    // ---- join CSR branch, attention pass 1 ----
    cudaStreamWaitEvent(0, evCsr, 0);
    launch_pdl(k_keep<true>, PGRID, TB, (cudaStream_t)0, src, dst, Wd, bd);
    launch_pdl(k_fin, gb_node4, TB, (cudaStream_t)0);

    // ---- join gemm1, conv1 aggregate ----
    cudaStreamWaitEvent(0, ev1, 0);
    launch_pdl(k_agg_h, PGRID, TB, (cudaStream_t)0, b1);

    // ---- fork: gemm2 on s1 (depends only on h, W2) ----
    cudaEventRecord(ev2, 0);
    cudaStreamWaitEvent(s1, ev2, 0);
    k_gemm<NH, NC><<<gb_gemm, 128, 0, s1>>>(p_h, W2, p_hw2);
    cudaEventRecord(ev3, s1);

    // ---- main chain: attention pass 2 ----
    launch_pdl(k_sim2, PGRID, TB, (cudaStream_t)0, src, dst);
    launch_pdl(k_keep<false>, PGRID, TB, (cudaStream_t)0, src, dst, Wd, bd);
    launch_pdl(k_fin, gb_node4, TB, (cudaStream_t)0);

    // ---- join gemm2, conv2 aggregate + log_softmax ----
    cudaStreamWaitEvent(0, ev3, 0);
    launch_pdl(k_agg_out, PGRID, TB, (cudaStream_t)0, b2, out);

    // Destroy host-side objects only when not inside a capture.
    cudaStreamCaptureStatus cs = cudaStreamCaptureStatusNone;
    cudaStreamIsCapturing((cudaStream_t)0, &cs);
    if (cs == cudaStreamCaptureStatusNone) {
        cudaEventDestroy(ev0); cudaEventDestroy(ev1);
        cudaEventDestroy(ev2); cudaEventDestroy(ev3);
        cudaEventDestroy(evCsr);
        cudaStreamDestroy(s1); cudaStreamDestroy(s2);
    }
}

// round 16
// speedup vs baseline: 1.1201x; 1.0329x over previous
#include <cuda_runtime.h>
#include <math.h>

#define NN 100000
#define NE 1000000
#define EH 500000
#define NF 128
#define NH 64
#define NC 40
#define PGRID 1184   // 8 blocks/SM × 148 SMs

typedef unsigned long long ULL;

// ---------------- scratch (device globals; zero-initialized at load) --------
__device__ float g_inv[NN];
__device__ float g_rowsum[NN];    // zeroed by agg epilogues each pass/replay
__device__ float g_ws[NN];
__device__ float g_dis[NN];
__device__ float g_sim[NE];
__device__ unsigned char g_mask[NE];  // pass-1 survivor mask
__device__ float2 g_csrw[NE];     // CSR slot: {in-weight, out-weight}
__device__ int   g_pos[NE];       // edge -> CSR slot
__device__ int   g_srccs[NE];     // CSR-ordered source node
__device__ float g_hw[NN * NH];
__device__ float g_h[NN * NH];
__device__ float g_hw2[NN * NC];
__device__ int g_cnt[NN];         // zeroed by agg_out epilogue each replay
__device__ int g_rowstart[NN];
__device__ int g_cursor[NN];
__device__ int g_bsum[128];

__device__ __forceinline__ float warp_red_sum(float v, int width) {
    for (int o = width >> 1; o; o >>= 1) v += __shfl_xor_sync(0xffffffffu, v, o);
    return v;
}
__device__ __forceinline__ float warp_red_max(float v, int width) {
    for (int o = width >> 1; o; o >>= 1) v = fmaxf(v, __shfl_xor_sync(0xffffffffu, v, o));
    return v;
}
__device__ __forceinline__ ULL pack2(float lo, float hi) {
    ULL r; asm("mov.b64 %0, {%1, %2};" : "=l"(r) : "f"(lo), "f"(hi)); return r;
}
__device__ __forceinline__ void ffma2(ULL& d, ULL a, ULL b) {
    asm("fma.rn.f32x2 %0, %1, %2, %0;" : "+l"(d) : "l"(a), "l"(b));
}
__device__ __forceinline__ float2 unpack2(ULL v) {
    float2 r; asm("mov.b64 {%0, %1}, %2;" : "=f"(r.x), "=f"(r.y) : "l"(v)); return r;
}

// ---------------- CSR build (side-stream branch) -----------------------------
__global__ void k_hist(const int* __restrict__ dst) {
    int e = blockIdx.x * blockDim.x + threadIdx.x;
    if (e < NE) atomicAdd(&g_cnt[dst[e]], 1);
}

__global__ void k_scan1() {
    cudaGridDependencySynchronize();
    int i = blockIdx.x * 1024 + threadIdx.x;
    int v = (i < NN) ? g_cnt[i] : 0;
    int lane = threadIdx.x & 31, wid = threadIdx.x >> 5;
    int x = v;
#pragma unroll
    for (int o = 1; o < 32; o <<= 1) {
        int t = __shfl_up_sync(0xffffffffu, x, o);
        if (lane >= o) x += t;
    }
    __shared__ int ws[32];
    if (lane == 31) ws[wid] = x;
    __syncthreads();
    if (wid == 0) {
        int y = ws[lane];
#pragma unroll
        for (int o = 1; o < 32; o <<= 1) {
            int t = __shfl_up_sync(0xffffffffu, y, o);
            if (lane >= o) y += t;
        }
        ws[lane] = y;
    }
    __syncthreads();
    int excl = x - v + (wid ? ws[wid - 1] : 0);
    if (i < NN) g_rowstart[i] = excl;
    if (threadIdx.x == 1023) g_bsum[blockIdx.x] = excl + v;
}

__global__ void k_scan3() {
    cudaGridDependencySynchronize();
    __shared__ int s_off;
    int blk = blockIdx.x >> 2;
    if (threadIdx.x < 32) {
        int acc = 0;
        for (int j = threadIdx.x; j < blk; j += 32) acc += g_bsum[j];
#pragma unroll
        for (int o = 16; o; o >>= 1) acc += __shfl_xor_sync(0xffffffffu, acc, o);
        if (threadIdx.x == 0) s_off = acc;
    }
    __syncthreads();
    int i = blockIdx.x * 256 + threadIdx.x;
    if (i < NN) {
        int rs = g_rowstart[i] + s_off;
        g_rowstart[i] = rs;
        g_cursor[i] = rs;
    }
}

__global__ void k_scatter(const int* __restrict__ src, const int* __restrict__ dst) {
    cudaGridDependencySynchronize();
    int e = blockIdx.x * blockDim.x + threadIdx.x;
    if (e >= EH) return;
    int s = src[e], d = dst[e];
    int p = atomicAdd(&g_cursor[d], 1);
    g_pos[e] = p; g_srccs[p] = s;
    int q = atomicAdd(&g_cursor[s], 1);
    g_pos[e + EH] = q; g_srccs[q] = d;
}

// ---- edge cosine sim on x: 8 lanes/pair, grid-stride, norms in-flight -------
__global__ void k_sim1(const float* __restrict__ X,
                       const int* __restrict__ src, const int* __restrict__ dst) {
    int lane = threadIdx.x & 7;
    int groups = (gridDim.x * blockDim.x) >> 3;
    for (int e = (blockIdx.x * blockDim.x + threadIdx.x) >> 3; e < EH; e += groups) {
        int s = src[e], d = dst[e];
        const float4* A = reinterpret_cast<const float4*>(X) + (size_t)s * 32;
        const float4* B = reinterpret_cast<const float4*>(X) + (size_t)d * 32;
        float pc = 0.f, ps = 0.f, pd = 0.f;
#pragma unroll
        for (int j = 0; j < 4; j++) {
            float4 a = A[lane + 8 * j];
            float4 b = B[lane + 8 * j];
            pc += a.x * b.x + a.y * b.y + a.z * b.z + a.w * b.w;
            ps += a.x * a.x + a.y * a.y + a.z * a.z + a.w * a.w;
            pd += b.x * b.x + b.y * b.y + b.z * b.z + b.w * b.w;
        }
        pc = warp_red_sum(pc, 8);
        ps = warp_red_sum(ps, 8);
        pd = warp_red_sum(pd, 8);
        if (lane == 0) {
            float is = (ps > 0.f) ? rsqrtf(ps) : 1.f;
            float id = (pd > 0.f) ? rsqrtf(pd) : 1.f;
            float raw = pc * is * id;
            if (raw < 0.1f) raw = 0.f;
            g_sim[e] = raw;   // symmetric in pass 1; keep mirrors
            if (raw > 0.f) {
                atomicAdd(&g_rowsum[s], raw);
                atomicAdd(&g_rowsum[d], raw);
            }
        }
    }
}

// ---- edge cosine sim on h: 8 lanes/pair, grid-stride, byte mask -------------
__global__ void k_sim2(const int* __restrict__ src, const int* __restrict__ dst) {
    cudaGridDependencySynchronize();
    int lane = threadIdx.x & 7;
    int groups = (gridDim.x * blockDim.x) >> 3;
    for (int e = (blockIdx.x * blockDim.x + threadIdx.x) >> 3; e < EH; e += groups) {
        int e2 = e + EH;
        bool m1 = g_mask[e] != 0, m2 = g_mask[e2] != 0;
        float p = 0.f;
        int s = 0, d = 0;
        if (m1 || m2) {
            s = src[e]; d = dst[e];
            const float4* A = reinterpret_cast<const float4*>(g_h) + (size_t)s * 16;
            const float4* B = reinterpret_cast<const float4*>(g_h) + (size_t)d * 16;
#pragma unroll
            for (int j = 0; j < 2; j++) {
                float4 a = A[lane + 8 * j];
                float4 b = B[lane + 8 * j];
                p += a.x * b.x + a.y * b.y + a.z * b.z + a.w * b.w;
            }
        }
        __syncwarp();
        p = warp_red_sum(p, 8);
        if (lane == 0) {
            if (!(m1 || m2)) { g_sim[e] = 0.f; g_sim[e2] = 0.f; continue; }
            float raw = p * g_inv[s] * g_inv[d];
            if (raw < 0.1f) raw = 0.f;
            float s1 = m1 ? raw : 0.f;
            float s2 = m2 ? raw : 0.f;
            g_sim[e] = s1;
            g_sim[e2] = s2;
            if (s1 > 0.f) atomicAdd(&g_rowsum[s], s1);
            if (s2 > 0.f) atomicAdd(&g_rowsum[d], s2);
        }
    }
}

// ------- learnable drop; writes {in,out} float2 to CSR slots, grid-stride ----
template <bool PASS1>
__global__ void k_keep(const int* __restrict__ src, const int* __restrict__ dst,
                       const float* __restrict__ Wd, const float* __restrict__ bd) {
    cudaGridDependencySynchronize();
    int stride = gridDim.x * blockDim.x;
    for (int e = blockIdx.x * blockDim.x + threadIdx.x; e < EH; e += stride) {
        int e2 = e + EH;
        float sf, sb;
        if (PASS1) { sf = g_sim[e]; sb = sf; }
        else       { sf = g_sim[e]; sb = g_sim[e2]; }
        int p1 = g_pos[e], p2 = g_pos[e2];
        if (!(sf > 0.f) && !(sb > 0.f)) {
            g_csrw[p1] = make_float2(0.f, 0.f);
            g_csrw[p2] = make_float2(0.f, 0.f);
            if (PASS1) { g_mask[e] = 0; g_mask[e2] = 0; }
            continue;
        }
        int s = src[e], d = dst[e];
        float rs = g_rowsum[s]; rs = (rs == 0.f) ? 1.f : rs;
        float rd = g_rowsum[d]; rd = (rd == 0.f) ? 1.f : rd;
        float af = sf / rs, ab = sb / rd;
        float w0 = Wd[0], w1 = Wd[1], bb = bd[0];
        float zf = af * w0 + ab * w1 + bb;
        float zb = ab * w0 + af * w1 + bb;
        float wf = (zf > 0.f && af > 0.f) ? expf(af) : 0.f;
        float wb = (zb > 0.f && ab > 0.f) ? expf(ab) : 0.f;
        g_csrw[p1] = make_float2(wf, wb);
        g_csrw[p2] = make_float2(wb, wf);
        if (PASS1) {
            g_mask[e]  = (wf > 0.f) ? 1 : 0;
            g_mask[e2] = (wb > 0.f) ? 1 : 0;
        }
    }
}

// ---- finalize per node: degC/degA from CSR row sums -> ws, dis --------------
__global__ void k_fin() {
    cudaGridDependencySynchronize();
    int g = blockIdx.x * blockDim.x + threadIdx.x;
    int node = g >> 2, lane = g & 3;
    if (node >= NN) return;
    int st = g_rowstart[node], cn = g_cnt[node];
    float sw = 0.f, sa = 0.f;
    for (int i = lane; i < cn; i += 4) {
        float2 w = g_csrw[st + i];
        sw += w.x;
        sa += (w.y != 0.f) ? 1.f : 0.f;
    }
    __syncwarp();
    sw = warp_red_sum(sw, 4);
    sa = warp_red_sum(sa, 4);
    if (lane == 0) {
        float lam = 1.f / (sa + 1.f);
        float w = expf(lam);
        g_ws[node] = w;
        g_dis[node] = rsqrtf(sw + w + 1.f);
    }
}

// -------- GEMM Y[n,M] = X[n,K] @ W[K,M] with packed f32x2 FMA ----------------
template <int K, int M>
__global__ void k_gemm(const float* __restrict__ X, const float* __restrict__ W,
                       float* __restrict__ Y) {
    __shared__ __align__(16) float Ws[K][M];
    __shared__ float xs[128][17];
    int tid = threadIdx.x;
    int node = blockIdx.x * 128 + tid;
    for (int i = tid; i < K * M; i += 128) Ws[i / M][i % M] = W[i];
    ULL acc[M / 2];
#pragma unroll
    for (int j = 0; j < M / 2; j++) acc[j] = 0ull;
    __syncthreads();
    for (int kb = 0; kb < K; kb += 16) {
#pragma unroll
        for (int t = 0; t < 16; t++) {
            int idx = t * 128 + tid;
            int r = idx >> 4, c = idx & 15;
            int nd = blockIdx.x * 128 + r;
            xs[r][c] = (nd < NN) ? X[(size_t)nd * K + kb + c] : 0.f;
        }
        __syncthreads();
#pragma unroll
        for (int k = 0; k < 16; k++) {
            float xv = xs[tid][k];
            ULL x2 = pack2(xv, xv);
            const ULL* wrow = reinterpret_cast<const ULL*>(&Ws[kb + k][0]);
#pragma unroll
            for (int j = 0; j < M / 2; j++) ffma2(acc[j], wrow[j], x2);
        }
        __syncthreads();
    }
    if (node < NN) {
#pragma unroll
        for (int j = 0; j < M / 2; j += 2) {
            float2 lo = unpack2(acc[j]), hi = unpack2(acc[j + 1]);
            *reinterpret_cast<float4*>(&Y[(size_t)node * M + 2 * j]) =
                make_float4(lo.x, lo.y, hi.x, hi.y);
        }
    }
}

// ---- conv1 agg (grid-stride, 16 lanes/node) + bias+relu + pass-2 norm -------
__global__ void k_agg_h(const float* __restrict__ b1) {
    cudaGridDependencySynchronize();
    int lane = threadIdx.x & 15;
    int groups = (gridDim.x * blockDim.x) >> 4;
    const float4* hw4 = reinterpret_cast<const float4*>(g_hw);
    for (int node = (blockIdx.x * blockDim.x + threadIdx.x) >> 4; node < NN;
         node += groups) {
        float dd = g_dis[node];
        float self = dd * (g_ws[node] + 1.f);
        float4 v = hw4[node * 16 + lane];
        float4 a  = make_float4(self * v.x, self * v.y, self * v.z, self * v.w);
        float4 a2 = make_float4(0.f, 0.f, 0.f, 0.f);
        int st = g_rowstart[node], cn = g_cnt[node];
        int i = 0;
        for (; i + 1 < cn; i += 2) {
            float w0 = g_csrw[st + i].x, w1v = g_csrw[st + i + 1].x;
            int   s0 = g_srccs[st + i],  s1v = g_srccs[st + i + 1];
            float c0 = g_dis[s0] * w0;
            float c1 = g_dis[s1v] * w1v;
            float4 u0 = hw4[(size_t)s0 * 16 + lane];
            float4 u1 = hw4[(size_t)s1v * 16 + lane];
            a.x  += c0 * u0.x; a.y  += c0 * u0.y; a.z  += c0 * u0.z; a.w  += c0 * u0.w;
            a2.x += c1 * u1.x; a2.y += c1 * u1.y; a2.z += c1 * u1.z; a2.w += c1 * u1.w;
        }
        if (i < cn) {
            float w0 = g_csrw[st + i].x;
            int s0 = g_srccs[st + i];
            float c0 = g_dis[s0] * w0;
            float4 u0 = hw4[(size_t)s0 * 16 + lane];
            a.x += c0 * u0.x; a.y += c0 * u0.y; a.z += c0 * u0.z; a.w += c0 * u0.w;
        }
        a.x += a2.x; a.y += a2.y; a.z += a2.z; a.w += a2.w;
        float4 b = reinterpret_cast<const float4*>(b1)[lane];
        float4 h;
        h.x = fmaxf(dd * a.x + b.x, 0.f);
        h.y = fmaxf(dd * a.y + b.y, 0.f);
        h.z = fmaxf(dd * a.z + b.z, 0.f);
        h.w = fmaxf(dd * a.w + b.w, 0.f);
        reinterpret_cast<float4*>(g_h)[node * 16 + lane] = h;
        float ss = h.x * h.x + h.y * h.y + h.z * h.z + h.w * h.w;
        __syncwarp();
        ss = warp_red_sum(ss, 16);
        if (lane == 0) {
            g_inv[node] = (ss == 0.f) ? 1.f : rsqrtf(ss);
            g_rowsum[node] = 0.f;
        }
    }
}

// ---- conv2 agg + bias + log_softmax, grid-stride, 8 lanes/node --------------
__global__ void k_agg_out(const float* __restrict__ b2, float* __restrict__ out) {
    cudaGridDependencySynchronize();
    int lane = threadIdx.x & 7;
    int groups = (gridDim.x * blockDim.x) >> 3;
    const float* hp = g_hw2;
    for (int node = (blockIdx.x * blockDim.x + threadIdx.x) >> 3; node < NN;
         node += groups) {
        float dd = g_dis[node];
        float self = dd * (g_ws[node] + 1.f);
        const float* row = hp + (size_t)node * NC;
        float4 v4 = *reinterpret_cast<const float4*>(row + lane * 4);
        float  v1 = row[32 + lane];
        float4 a4 = make_float4(self * v4.x, self * v4.y, self * v4.z, self * v4.w);
        float  a1 = self * v1;
        int st = g_rowstart[node], cn = g_cnt[node];
        int i = 0;
        for (; i + 1 < cn; i += 2) {
            float w0 = g_csrw[st + i].x, w1v = g_csrw[st + i + 1].x;
            int   s0 = g_srccs[st + i],  s1v = g_srccs[st + i + 1];
            float c0 = g_dis[s0] * w0;
            float c1 = g_dis[s1v] * w1v;
            const float* r0 = hp + (size_t)s0 * NC;
            const float* r1 = hp + (size_t)s1v * NC;
            float4 u0 = *reinterpret_cast<const float4*>(r0 + lane * 4);
            float4 u1 = *reinterpret_cast<const float4*>(r1 + lane * 4);
            float  e0 = r0[32 + lane];
            float  e1 = r1[32 + lane];
            a4.x += c0 * u0.x; a4.y += c0 * u0.y; a4.z += c0 * u0.z; a4.w += c0 * u0.w;
            a1   += c0 * e0;
            a4.x += c1 * u1.x; a4.y += c1 * u1.y; a4.z += c1 * u1.z; a4.w += c1 * u1.w;
            a1   += c1 * e1;
        }
        if (i < cn) {
            float w0 = g_csrw[st + i].x;
            int s0 = g_srccs[st + i];
            float c0 = g_dis[s0] * w0;
            const float* r0 = hp + (size_t)s0 * NC;
            float4 u0 = *reinterpret_cast<const float4*>(r0 + lane * 4);
            float  e0 = r0[32 + lane];
            a4.x += c0 * u0.x; a4.y += c0 * u0.y; a4.z += c0 * u0.z; a4.w += c0 * u0.w;
            a1   += c0 * e0;
        }
        float4 bb4 = *reinterpret_cast<const float4*>(b2 + lane * 4);
        float  bb1 = b2[32 + lane];
        float4 o4;
        o4.x = dd * a4.x + bb4.x; o4.y = dd * a4.y + bb4.y;
        o4.z = dd * a4.z + bb4.z; o4.w = dd * a4.w + bb4.w;
        float o1 = dd * a1 + bb1;
        float mx = fmaxf(fmaxf(fmaxf(o4.x, o4.y), fmaxf(o4.z, o4.w)), o1);
        __syncwarp();
        float m = warp_red_max(mx, 8);
        float es = expf(o4.x - m) + expf(o4.y - m) + expf(o4.z - m) + expf(o4.w - m)
                 + expf(o1 - m);
        es = warp_red_sum(es, 8);
        float lse = logf(es) + m;
        float* orow = out + (size_t)node * NC;
        *reinterpret_cast<float4*>(orow + lane * 4) =
            make_float4(o4.x - lse, o4.y - lse, o4.z - lse, o4.w - lse);
        orow[32 + lane] = o1 - lse;
        if (lane == 0) {   // re-arm for the next replay
            g_cnt[node] = 0;
            g_rowsum[node] = 0.f;
        }
    }
}

// ---------------- PDL launch helper -------------------------------------------
template <typename F, typename... Args>
static void launch_pdl(F kern, int grid, int block, cudaStream_t st, Args... args) {
    cudaLaunchConfig_t cfg = {};
    cfg.gridDim = dim3(grid, 1, 1);
    cfg.blockDim = dim3(block, 1, 1);
    cfg.stream = st;
    cudaLaunchAttribute attr[1];
    attr[0].id = cudaLaunchAttributeProgrammaticStreamSerialization;
    attr[0].val.programmaticStreamSerializationAllowed = 1;
    cfg.attrs = attr;
    cfg.numAttrs = 1;
    cudaLaunchKernelEx(&cfg, kern, args...);
}

// ---------------- host driver (sim1-first capture order + low-prio forks) ----
extern "C" void kernel_launch(void* const* d_in, const int* in_sizes, int n_in,
                              void* d_out, int out_size) {
    const float* x  = (const float*)d_in[0];
    const int* src  = (const int*)d_in[1];
    const int* dst  = (const int*)d_in[2];
    const float* W1 = (const float*)d_in[4];
    const float* b1 = (const float*)d_in[5];
    const float* W2 = (const float*)d_in[6];
    const float* b2 = (const float*)d_in[7];
    const float* Wd = (const float*)d_in[8];
    const float* bd = (const float*)d_in[9];
    float* out = (float*)d_out;

    float *p_hw, *p_h, *p_hw2;
    cudaGetSymbolAddress((void**)&p_hw,  g_hw);
    cudaGetSymbolAddress((void**)&p_h,   g_h);
    cudaGetSymbolAddress((void**)&p_hw2, g_hw2);

    const int TB = 256;
    int gb_node4 = (NN * 4 + TB - 1) / TB;
    int gb_edge  = (NE + TB - 1) / TB;
    int gb_pair  = (EH + TB - 1) / TB;
    int gb_gemm  = (NN + 127) / 128;
    int nb_scan  = (NN + 1023) / 1024;

    int prLo = 0, prHi = 0;
    cudaDeviceGetStreamPriorityRange(&prLo, &prHi);  // prLo = least priority
    cudaStream_t s1, s2;
    cudaStreamCreateWithPriority(&s1, cudaStreamNonBlocking, prLo);
    cudaStreamCreateWithPriority(&s2, cudaStreamNonBlocking, prLo);
    cudaEvent_t ev0, ev1, ev2, ev3, evCsr;
    cudaEventCreateWithFlags(&ev0,   cudaEventDisableTiming);
    cudaEventCreateWithFlags(&ev1,   cudaEventDisableTiming);
    cudaEventCreateWithFlags(&ev2,   cudaEventDisableTiming);
    cudaEventCreateWithFlags(&ev3,   cudaEventDisableTiming);
    cudaEventCreateWithFlags(&evCsr, cudaEventDisableTiming);

    // ---- fork point (captured before any kernel) ----
    cudaEventRecord(ev0, 0);

    // ---- main chain FIRST in capture order: sim1 owns the machine ----
    k_sim1<<<PGRID, TB>>>(x, src, dst);

    // ---- fork A: gemm1 on low-prio s1 (depends only on x, W1) ----
    cudaStreamWaitEvent(s1, ev0, 0);
    k_gemm<NF, NH><<<gb_gemm, 128, 0, s1>>>(x, W1, p_hw);
    cudaEventRecord(ev1, s1);

    // ---- fork B: CSR build on low-prio s2 (hidden under sim1) ----
    cudaStreamWaitEvent(s2, ev0, 0);
    k_hist<<<gb_edge, TB, 0, s2>>>(dst);
    launch_pdl(k_scan1, nb_scan, 1024, s2);
    launch_pdl(k_scan3, (NN + 255) / 256, 256, s2);
    launch_pdl(k_scatter, gb_pair, TB, s2, src, dst);
    cudaEventRecord(evCsr, s2);

    // ---- join CSR branch, attention pass 1 ----
    cudaStreamWaitEvent(0, evCsr, 0);
    launch_pdl(k_keep<true>, PGRID, TB, (cudaStream_t)0, src, dst, Wd, bd);
    launch_pdl(k_fin, gb_node4, TB, (cudaStream_t)0);

    // ---- join gemm1, conv1 aggregate ----
    cudaStreamWaitEvent(0, ev1, 0);
    launch_pdl(k_agg_h, PGRID, TB, (cudaStream_t)0, b1);

    // ---- fork: gemm2 on s1 (depends only on h, W2) ----
    cudaEventRecord(ev2, 0);
    cudaStreamWaitEvent(s1, ev2, 0);
    k_gemm<NH, NC><<<gb_gemm, 128, 0, s1>>>(p_h, W2, p_hw2);
    cudaEventRecord(ev3, s1);

    // ---- main chain: attention pass 2 ----
    launch_pdl(k_sim2, PGRID, TB, (cudaStream_t)0, src, dst);
    launch_pdl(k_keep<false>, PGRID, TB, (cudaStream_t)0, src, dst, Wd, bd);
    launch_pdl(k_fin, gb_node4, TB, (cudaStream_t)0);

    // ---- join gemm2, conv2 aggregate + log_softmax ----
    cudaStreamWaitEvent(0, ev3, 0);
    launch_pdl(k_agg_out, PGRID, TB, (cudaStream_t)0, b2, out);

    // Destroy host-side objects only when not inside a capture.
    cudaStreamCaptureStatus cs = cudaStreamCaptureStatusNone;
    cudaStreamIsCapturing((cudaStream_t)0, &cs);
    if (cs == cudaStreamCaptureStatusNone) {
        cudaEventDestroy(ev0); cudaEventDestroy(ev1);
        cudaEventDestroy(ev2); cudaEventDestroy(ev3);
        cudaEventDestroy(evCsr);
        cudaStreamDestroy(s1); cudaStreamDestroy(s2);
    }
}

// round 17
// speedup vs baseline: 1.1291x; 1.0081x over previous
#include <cuda_runtime.h>
#include <math.h>

#define NN 100000
#define NE 1000000
#define EH 500000
#define NF 128
#define NH 64
#define NC 40
#define PGRID 1184   // 8 blocks/SM × 148 SMs

typedef unsigned long long ULL;

// ---------------- scratch (device globals; zero-initialized at load) --------
__device__ float g_inv[NN];
__device__ float g_rowsum[NN];    // zeroed by agg epilogues each pass/replay
__device__ float g_ws[NN];
__device__ float g_dis[NN];
__device__ float g_sim[NE];
__device__ unsigned char g_mask[NE];  // pass-1 survivor mask
__device__ float2 g_csrw[NE];     // CSR slot: {in-weight, out-weight}
__device__ int2  g_pos2[EH];      // pair -> {fwd slot, bwd slot}
__device__ int   g_srccs[NE];     // CSR-ordered source node
__device__ float g_hw[NN * NH];
__device__ float g_h[NN * NH];
__device__ float g_hw2[NN * NC];
__device__ int g_cnt[NN];         // zeroed by agg_out epilogue each replay
__device__ int g_rowstart[NN];
__device__ int g_cursor[NN];
__device__ int g_total;           // alloc cursor; zeroed by agg_out epilogue

__device__ __forceinline__ float warp_red_sum(float v, int width) {
    for (int o = width >> 1; o; o >>= 1) v += __shfl_xor_sync(0xffffffffu, v, o);
    return v;
}
__device__ __forceinline__ float warp_red_max(float v, int width) {
    for (int o = width >> 1; o; o >>= 1) v = fmaxf(v, __shfl_xor_sync(0xffffffffu, v, o));
    return v;
}
__device__ __forceinline__ ULL pack2(float lo, float hi) {
    ULL r; asm("mov.b64 %0, {%1, %2};" : "=l"(r) : "f"(lo), "f"(hi)); return r;
}
__device__ __forceinline__ void ffma2(ULL& d, ULL a, ULL b) {
    asm("fma.rn.f32x2 %0, %1, %2, %0;" : "+l"(d) : "l"(a), "l"(b));
}
__device__ __forceinline__ float2 unpack2(ULL v) {
    float2 r; asm("mov.b64 {%0, %1}, %2;" : "=f"(r.x), "=f"(r.y) : "l"(v)); return r;
}

// ---------------- CSR build (side-stream branch) -----------------------------
__global__ void k_hist(const int* __restrict__ dst) {
    int e = blockIdx.x * blockDim.x + threadIdx.x;
    if (e < NE) atomicAdd(&g_cnt[dst[e]], 1);
}

// single-pass row allocation: contiguous per-row ranges, arbitrary row order
__global__ void k_alloc() {
    cudaGridDependencySynchronize();
    int i = blockIdx.x * blockDim.x + threadIdx.x;
    if (i >= NN) return;
    int c = g_cnt[i];
    int st = atomicAdd(&g_total, c);
    g_rowstart[i] = st;
    g_cursor[i] = st;
}

__global__ void k_scatter(const int* __restrict__ src, const int* __restrict__ dst) {
    cudaGridDependencySynchronize();
    int e = blockIdx.x * blockDim.x + threadIdx.x;
    if (e >= EH) return;
    int s = src[e], d = dst[e];
    int p = atomicAdd(&g_cursor[d], 1);
    g_srccs[p] = s;
    int q = atomicAdd(&g_cursor[s], 1);
    g_srccs[q] = d;
    g_pos2[e] = make_int2(p, q);
}

// ---- edge cosine sim on x: 8 lanes/pair, grid-stride, norms in-flight -------
__global__ void k_sim1(const float* __restrict__ X,
                       const int* __restrict__ src, const int* __restrict__ dst) {
    int lane = threadIdx.x & 7;
    int groups = (gridDim.x * blockDim.x) >> 3;
    for (int e = (blockIdx.x * blockDim.x + threadIdx.x) >> 3; e < EH; e += groups) {
        int s = src[e], d = dst[e];
        const float4* A = reinterpret_cast<const float4*>(X) + (size_t)s * 32;
        const float4* B = reinterpret_cast<const float4*>(X) + (size_t)d * 32;
        float pc = 0.f, ps = 0.f, pd = 0.f;
#pragma unroll
        for (int j = 0; j < 4; j++) {
            float4 a = A[lane + 8 * j];
            float4 b = B[lane + 8 * j];
            pc += a.x * b.x + a.y * b.y + a.z * b.z + a.w * b.w;
            ps += a.x * a.x + a.y * a.y + a.z * a.z + a.w * a.w;
            pd += b.x * b.x + b.y * b.y + b.z * b.z + b.w * b.w;
        }
        pc = warp_red_sum(pc, 8);
        ps = warp_red_sum(ps, 8);
        pd = warp_red_sum(pd, 8);
        if (lane == 0) {
            float is = (ps > 0.f) ? rsqrtf(ps) : 1.f;
            float id = (pd > 0.f) ? rsqrtf(pd) : 1.f;
            float raw = pc * is * id;
            if (raw < 0.1f) raw = 0.f;
            __stcs(&g_sim[e], raw);   // single-use stream: evict-first
            if (raw > 0.f) {
                atomicAdd(&g_rowsum[s], raw);
                atomicAdd(&g_rowsum[d], raw);
            }
        }
    }
}

// ---- edge cosine sim on h: 8 lanes/pair, grid-stride, byte mask -------------
__global__ void k_sim2(const int* __restrict__ src, const int* __restrict__ dst) {
    cudaGridDependencySynchronize();
    int lane = threadIdx.x & 7;
    int groups = (gridDim.x * blockDim.x) >> 3;
    for (int e = (blockIdx.x * blockDim.x + threadIdx.x) >> 3; e < EH; e += groups) {
        int e2 = e + EH;
        bool m1 = g_mask[e] != 0, m2 = g_mask[e2] != 0;
        float p = 0.f;
        int s = 0, d = 0;
        if (m1 || m2) {
            s = src[e]; d = dst[e];
            const float4* A = reinterpret_cast<const float4*>(g_h) + (size_t)s * 16;
            const float4* B = reinterpret_cast<const float4*>(g_h) + (size_t)d * 16;
#pragma unroll
            for (int j = 0; j < 2; j++) {
                float4 a = A[lane + 8 * j];
                float4 b = B[lane + 8 * j];
                p += a.x * b.x + a.y * b.y + a.z * b.z + a.w * b.w;
            }
        }
        __syncwarp();
        p = warp_red_sum(p, 8);
        if (lane == 0) {
            if (!(m1 || m2)) {
                __stcs(&g_sim[e], 0.f); __stcs(&g_sim[e2], 0.f);
                continue;
            }
            float raw = p * g_inv[s] * g_inv[d];
            if (raw < 0.1f) raw = 0.f;
            float s1 = m1 ? raw : 0.f;
            float s2 = m2 ? raw : 0.f;
            __stcs(&g_sim[e], s1);
            __stcs(&g_sim[e2], s2);
            if (s1 > 0.f) atomicAdd(&g_rowsum[s], s1);
            if (s2 > 0.f) atomicAdd(&g_rowsum[d], s2);
        }
    }
}

// ------- learnable drop; writes {in,out} float2 to CSR slots, grid-stride ----
template <bool PASS1>
__global__ void k_keep(const int* __restrict__ src, const int* __restrict__ dst,
                       const float* __restrict__ Wd, const float* __restrict__ bd) {
    cudaGridDependencySynchronize();
    int stride = gridDim.x * blockDim.x;
    for (int e = blockIdx.x * blockDim.x + threadIdx.x; e < EH; e += stride) {
        int e2 = e + EH;
        float sf, sb;
        if (PASS1) { sf = __ldcs(&g_sim[e]); sb = sf; }
        else       { sf = __ldcs(&g_sim[e]); sb = __ldcs(&g_sim[e2]); }
        int2 pp = g_pos2[e];
        if (!(sf > 0.f) && !(sb > 0.f)) {
            g_csrw[pp.x] = make_float2(0.f, 0.f);
            g_csrw[pp.y] = make_float2(0.f, 0.f);
            if (PASS1) { g_mask[e] = 0; g_mask[e2] = 0; }
            continue;
        }
        int s = src[e], d = dst[e];
        float rs = g_rowsum[s]; rs = (rs == 0.f) ? 1.f : rs;
        float rd = g_rowsum[d]; rd = (rd == 0.f) ? 1.f : rd;
        float af = sf / rs, ab = sb / rd;
        float w0 = Wd[0], w1 = Wd[1], bb = bd[0];
        float zf = af * w0 + ab * w1 + bb;
        float zb = ab * w0 + af * w1 + bb;
        float wf = (zf > 0.f && af > 0.f) ? expf(af) : 0.f;
        float wb = (zb > 0.f && ab > 0.f) ? expf(ab) : 0.f;
        g_csrw[pp.x] = make_float2(wf, wb);
        g_csrw[pp.y] = make_float2(wb, wf);
        if (PASS1) {
            g_mask[e]  = (wf > 0.f) ? 1 : 0;
            g_mask[e2] = (wb > 0.f) ? 1 : 0;
        }
    }
}

// ---- finalize per node: degC/degA from CSR row sums -> ws, dis --------------
__global__ void k_fin() {
    cudaGridDependencySynchronize();
    int g = blockIdx.x * blockDim.x + threadIdx.x;
    int node = g >> 2, lane = g & 3;
    if (node >= NN) return;
    int st = g_rowstart[node], cn = g_cnt[node];
    float sw = 0.f, sa = 0.f;
    for (int i = lane; i < cn; i += 4) {
        float2 w = g_csrw[st + i];
        sw += w.x;
        sa += (w.y != 0.f) ? 1.f : 0.f;
    }
    __syncwarp();
    sw = warp_red_sum(sw, 4);
    sa = warp_red_sum(sa, 4);
    if (lane == 0) {
        float lam = 1.f / (sa + 1.f);
        float w = expf(lam);
        g_ws[node] = w;
        g_dis[node] = rsqrtf(sw + w + 1.f);
    }
}

// -------- GEMM Y[n,M] = X[n,K] @ W[K,M] with packed f32x2 FMA ----------------
template <int K, int M>
__global__ void k_gemm(const float* __restrict__ X, const float* __restrict__ W,
                       float* __restrict__ Y) {
    __shared__ __align__(16) float Ws[K][M];
    __shared__ float xs[128][17];
    int tid = threadIdx.x;
    int node = blockIdx.x * 128 + tid;
    for (int i = tid; i < K * M; i += 128) Ws[i / M][i % M] = W[i];
    ULL acc[M / 2];
#pragma unroll
    for (int j = 0; j < M / 2; j++) acc[j] = 0ull;
    __syncthreads();
    for (int kb = 0; kb < K; kb += 16) {
#pragma unroll
        for (int t = 0; t < 16; t++) {
            int idx = t * 128 + tid;
            int r = idx >> 4, c = idx & 15;
            int nd = blockIdx.x * 128 + r;
            xs[r][c] = (nd < NN) ? X[(size_t)nd * K + kb + c] : 0.f;
        }
        __syncthreads();
#pragma unroll
        for (int k = 0; k < 16; k++) {
            float xv = xs[tid][k];
            ULL x2 = pack2(xv, xv);
            const ULL* wrow = reinterpret_cast<const ULL*>(&Ws[kb + k][0]);
#pragma unroll
            for (int j = 0; j < M / 2; j++) ffma2(acc[j], wrow[j], x2);
        }
        __syncthreads();
    }
    if (node < NN) {
#pragma unroll
        for (int j = 0; j < M / 2; j += 2) {
            float2 lo = unpack2(acc[j]), hi = unpack2(acc[j + 1]);
            *reinterpret_cast<float4*>(&Y[(size_t)node * M + 2 * j]) =
                make_float4(lo.x, lo.y, hi.x, hi.y);
        }
    }
}

// ---- conv1 agg (grid-stride, 16 lanes/node) + bias+relu + pass-2 norm -------
__global__ void k_agg_h(const float* __restrict__ b1) {
    cudaGridDependencySynchronize();
    int lane = threadIdx.x & 15;
    int groups = (gridDim.x * blockDim.x) >> 4;
    const float4* hw4 = reinterpret_cast<const float4*>(g_hw);
    for (int node = (blockIdx.x * blockDim.x + threadIdx.x) >> 4; node < NN;
         node += groups) {
        float dd = g_dis[node];
        float self = dd * (g_ws[node] + 1.f);
        float4 v = hw4[node * 16 + lane];
        float4 a  = make_float4(self * v.x, self * v.y, self * v.z, self * v.w);
        float4 a2 = make_float4(0.f, 0.f, 0.f, 0.f);
        int st = g_rowstart[node], cn = g_cnt[node];
        int i = 0;
        for (; i + 1 < cn; i += 2) {
            float w0 = g_csrw[st + i].x, w1v = g_csrw[st + i + 1].x;
            int   s0 = g_srccs[st + i],  s1v = g_srccs[st + i + 1];
            float c0 = g_dis[s0] * w0;
            float c1 = g_dis[s1v] * w1v;
            float4 u0 = hw4[(size_t)s0 * 16 + lane];
            float4 u1 = hw4[(size_t)s1v * 16 + lane];
            a.x  += c0 * u0.x; a.y  += c0 * u0.y; a.z  += c0 * u0.z; a.w  += c0 * u0.w;
            a2.x += c1 * u1.x; a2.y += c1 * u1.y; a2.z += c1 * u1.z; a2.w += c1 * u1.w;
        }
        if (i < cn) {
            float w0 = g_csrw[st + i].x;
            int s0 = g_srccs[st + i];
            float c0 = g_dis[s0] * w0;
            float4 u0 = hw4[(size_t)s0 * 16 + lane];
            a.x += c0 * u0.x; a.y += c0 * u0.y; a.z += c0 * u0.z; a.w += c0 * u0.w;
        }
        a.x += a2.x; a.y += a2.y; a.z += a2.z; a.w += a2.w;
        float4 b = reinterpret_cast<const float4*>(b1)[lane];
        float4 h;
        h.x = fmaxf(dd * a.x + b.x, 0.f);
        h.y = fmaxf(dd * a.y + b.y, 0.f);
        h.z = fmaxf(dd * a.z + b.z, 0.f);
        h.w = fmaxf(dd * a.w + b.w, 0.f);
        reinterpret_cast<float4*>(g_h)[node * 16 + lane] = h;
        float ss = h.x * h.x + h.y * h.y + h.z * h.z + h.w * h.w;
        __syncwarp();
        ss = warp_red_sum(ss, 16);
        if (lane == 0) {
            g_inv[node] = (ss == 0.f) ? 1.f : rsqrtf(ss);
            g_rowsum[node] = 0.f;
        }
    }
}

// ---- conv2 agg + bias + log_softmax, grid-stride, 8 lanes/node --------------
__global__ void k_agg_out(const float* __restrict__ b2, float* __restrict__ out) {
    cudaGridDependencySynchronize();
    int lane = threadIdx.x & 7;
    int groups = (gridDim.x * blockDim.x) >> 3;
    const float* hp = g_hw2;
    for (int node = (blockIdx.x * blockDim.x + threadIdx.x) >> 3; node < NN;
         node += groups) {
        float dd = g_dis[node];
        float self = dd * (g_ws[node] + 1.f);
        const float* row = hp + (size_t)node * NC;
        float4 v4 = *reinterpret_cast<const float4*>(row + lane * 4);
        float  v1 = row[32 + lane];
        float4 a4 = make_float4(self * v4.x, self * v4.y, self * v4.z, self * v4.w);
        float  a1 = self * v1;
        int st = g_rowstart[node], cn = g_cnt[node];
        int i = 0;
        for (; i + 1 < cn; i += 2) {
            float w0 = g_csrw[st + i].x, w1v = g_csrw[st + i + 1].x;
            int   s0 = g_srccs[st + i],  s1v = g_srccs[st + i + 1];
            float c0 = g_dis[s0] * w0;
            float c1 = g_dis[s1v] * w1v;
            const float* r0 = hp + (size_t)s0 * NC;
            const float* r1 = hp + (size_t)s1v * NC;
            float4 u0 = *reinterpret_cast<const float4*>(r0 + lane * 4);
            float4 u1 = *reinterpret_cast<const float4*>(r1 + lane * 4);
            float  e0 = r0[32 + lane];
            float  e1 = r1[32 + lane];
            a4.x += c0 * u0.x; a4.y += c0 * u0.y; a4.z += c0 * u0.z; a4.w += c0 * u0.w;
            a1   += c0 * e0;
            a4.x += c1 * u1.x; a4.y += c1 * u1.y; a4.z += c1 * u1.z; a4.w += c1 * u1.w;
            a1   += c1 * e1;
        }
        if (i < cn) {
            float w0 = g_csrw[st + i].x;
            int s0 = g_srccs[st + i];
            float c0 = g_dis[s0] * w0;
            const float* r0 = hp + (size_t)s0 * NC;
            float4 u0 = *reinterpret_cast<const float4*>(r0 + lane * 4);
            float  e0 = r0[32 + lane];
            a4.x += c0 * u0.x; a4.y += c0 * u0.y; a4.z += c0 * u0.z; a4.w += c0 * u0.w;
            a1   += c0 * e0;
        }
        float4 bb4 = *reinterpret_cast<const float4*>(b2 + lane * 4);
        float  bb1 = b2[32 + lane];
        float4 o4;
        o4.x = dd * a4.x + bb4.x; o4.y = dd * a4.y + bb4.y;
        o4.z = dd * a4.z + bb4.z; o4.w = dd * a4.w + bb4.w;
        float o1 = dd * a1 + bb1;
        float mx = fmaxf(fmaxf(fmaxf(o4.x, o4.y), fmaxf(o4.z, o4.w)), o1);
        __syncwarp();
        float m = warp_red_max(mx, 8);
        float es = expf(o4.x - m) + expf(o4.y - m) + expf(o4.z - m) + expf(o4.w - m)
                 + expf(o1 - m);
        es = warp_red_sum(es, 8);
        float lse = logf(es) + m;
        float* orow = out + (size_t)node * NC;
        *reinterpret_cast<float4*>(orow + lane * 4) =
            make_float4(o4.x - lse, o4.y - lse, o4.z - lse, o4.w - lse);
        orow[32 + lane] = o1 - lse;
        if (lane == 0) {   // re-arm for the next replay
            g_cnt[node] = 0;
            g_rowsum[node] = 0.f;
            if (node == 0) g_total = 0;
        }
    }
}

// ---------------- PDL launch helper -------------------------------------------
template <typename F, typename... Args>
static void launch_pdl(F kern, int grid, int block, cudaStream_t st, Args... args) {
    cudaLaunchConfig_t cfg = {};
    cfg.gridDim = dim3(grid, 1, 1);
    cfg.blockDim = dim3(block, 1, 1);
    cfg.stream = st;
    cudaLaunchAttribute attr[1];
    attr[0].id = cudaLaunchAttributeProgrammaticStreamSerialization;
    attr[0].val.programmaticStreamSerializationAllowed = 1;
    cfg.attrs = attr;
    cfg.numAttrs = 1;
    cudaLaunchKernelEx(&cfg, kern, args...);
}

// ---------------- host driver (sim1-first capture order + low-prio forks) ----
extern "C" void kernel_launch(void* const* d_in, const int* in_sizes, int n_in,
                              void* d_out, int out_size) {
    const float* x  = (const float*)d_in[0];
    const int* src  = (const int*)d_in[1];
    const int* dst  = (const int*)d_in[2];
    const float* W1 = (const float*)d_in[4];
    const float* b1 = (const float*)d_in[5];
    const float* W2 = (const float*)d_in[6];
    const float* b2 = (const float*)d_in[7];
    const float* Wd = (const float*)d_in[8];
    const float* bd = (const float*)d_in[9];
    float* out = (float*)d_out;

    float *p_hw, *p_h, *p_hw2;
    cudaGetSymbolAddress((void**)&p_hw,  g_hw);
    cudaGetSymbolAddress((void**)&p_h,   g_h);
    cudaGetSymbolAddress((void**)&p_hw2, g_hw2);

    const int TB = 256;
    int gb_node4 = (NN * 4 + TB - 1) / TB;
    int gb_node  = (NN + TB - 1) / TB;
    int gb_edge  = (NE + TB - 1) / TB;
    int gb_pair  = (EH + TB - 1) / TB;
    int gb_gemm  = (NN + 127) / 128;

    int prLo = 0, prHi = 0;
    cudaDeviceGetStreamPriorityRange(&prLo, &prHi);  // prLo = least priority
    cudaStream_t s1, s2;
    cudaStreamCreateWithPriority(&s1, cudaStreamNonBlocking, prLo);
    cudaStreamCreateWithPriority(&s2, cudaStreamNonBlocking, prLo);
    cudaEvent_t ev0, ev1, ev2, ev3, evCsr;
    cudaEventCreateWithFlags(&ev0,   cudaEventDisableTiming);
    cudaEventCreateWithFlags(&ev1,   cudaEventDisableTiming);
    cudaEventCreateWithFlags(&ev2,   cudaEventDisableTiming);
    cudaEventCreateWithFlags(&ev3,   cudaEventDisableTiming);
    cudaEventCreateWithFlags(&evCsr, cudaEventDisableTiming);

    // ---- fork point (captured before any kernel) ----
    cudaEventRecord(ev0, 0);

    // ---- main chain FIRST in capture order: sim1 owns the machine ----
    k_sim1<<<PGRID, TB>>>(x, src, dst);

    // ---- fork A: gemm1 on low-prio s1 (depends only on x, W1) ----
    cudaStreamWaitEvent(s1, ev0, 0);
    k_gemm<NF, NH><<<gb_gemm, 128, 0, s1>>>(x, W1, p_hw);
    cudaEventRecord(ev1, s1);

    // ---- fork B: CSR build on low-prio s2 (hist -> alloc -> scatter) ----
    cudaStreamWaitEvent(s2, ev0, 0);
    k_hist<<<gb_edge, TB, 0, s2>>>(dst);
    launch_pdl(k_alloc, gb_node, TB, s2);
    launch_pdl(k_scatter, gb_pair, TB, s2, src, dst);
    cudaEventRecord(evCsr, s2);

    // ---- join CSR branch, attention pass 1 ----
    cudaStreamWaitEvent(0, evCsr, 0);
    launch_pdl(k_keep<true>, PGRID, TB, (cudaStream_t)0, src, dst, Wd, bd);
    launch_pdl(k_fin, gb_node4, TB, (cudaStream_t)0);

    // ---- join gemm1, conv1 aggregate ----
    cudaStreamWaitEvent(0, ev1, 0);
    launch_pdl(k_agg_h, PGRID, TB, (cudaStream_t)0, b1);

    // ---- fork: gemm2 on s1 (depends only on h, W2) ----
    cudaEventRecord(ev2, 0);
    cudaStreamWaitEvent(s1, ev2, 0);
    k_gemm<NH, NC><<<gb_gemm, 128, 0, s1>>>(p_h, W2, p_hw2);
    cudaEventRecord(ev3, s1);

    // ---- main chain: attention pass 2 ----
    launch_pdl(k_sim2, PGRID, TB, (cudaStream_t)0, src, dst);
    launch_pdl(k_keep<false>, PGRID, TB, (cudaStream_t)0, src, dst, Wd, bd);
    launch_pdl(k_fin, gb_node4, TB, (cudaStream_t)0);

    // ---- join gemm2, conv2 aggregate + log_softmax ----
    cudaStreamWaitEvent(0, ev3, 0);
    launch_pdl(k_agg_out, PGRID, TB, (cudaStream_t)0, b2, out);

    // Destroy host-side objects only when not inside a capture.
    cudaStreamCaptureStatus cs = cudaStreamCaptureStatusNone;
    cudaStreamIsCapturing((cudaStream_t)0, &cs);
    if (cs == cudaStreamCaptureStatusNone) {
        cudaEventDestroy(ev0); cudaEventDestroy(ev1);
        cudaEventDestroy(ev2); cudaEventDestroy(ev3);
        cudaEventDestroy(evCsr);
        cudaStreamDestroy(s1); cudaStreamDestroy(s2);
    }
}